// round 1
// baseline (speedup 1.0000x reference)
#include <cuda_runtime.h>
#include <cstdint>

static constexpr int   kVocab   = 128000;
static constexpr int   kTopK    = 50;
static constexpr float kTopP    = 0.9f;
static constexpr float kNeg     = -1000000000.0f;
static constexpr int   kThreads = 1024;
static constexpr int   kCap     = 4096;   // candidate buffer capacity (shared)

// Order-preserving float -> uint32 key (monotone increasing).
__device__ __forceinline__ unsigned f2key(float f) {
    unsigned b = __float_as_uint(f);
    return (b & 0x80000000u) ? ~b : (b | 0x80000000u);
}
__device__ __forceinline__ float key2f(unsigned k) {
    unsigned b = (k & 0x80000000u) ? (k & 0x7FFFFFFFu) : ~k;
    return __uint_as_float(b);
}

__global__ void __launch_bounds__(kThreads, 1)
topk_topp_kernel(const float* __restrict__ in, float* __restrict__ out) {
    __shared__ unsigned long long s_cand[kCap];
    __shared__ float s_wm[32];       // sorted (ascending) warp maxima of samples
    __shared__ float s_ex[kTopK];    // exp(v - max) for top tokens
    __shared__ int   s_cnt;
    __shared__ float s_T;
    __shared__ int   s_k;

    const int row  = blockIdx.x;
    const float* rin  = in  + (long long)row * kVocab;
    float*       rout = out + (long long)row * kVocab;
    const int tid  = threadIdx.x;
    const int lane = tid & 31;
    const int wid  = tid >> 5;

    // ---------------- Phase 0: sample-based threshold estimate ----------------
    // 1024 strided samples -> 32 warp maxima -> sort 32 values in warp 0.
    float sv = rin[tid * (kVocab / kThreads)];
#pragma unroll
    for (int o = 16; o > 0; o >>= 1)
        sv = fmaxf(sv, __shfl_xor_sync(0xffffffffu, sv, o));
    if (lane == 0) s_wm[wid] = sv;
    __syncthreads();
    if (wid == 0) {
        float x = s_wm[lane];
#pragma unroll
        for (int k = 2; k <= 32; k <<= 1) {
#pragma unroll
            for (int j = k >> 1; j > 0; j >>= 1) {
                float y     = __shfl_xor_sync(0xffffffffu, x, j);
                bool  up    = ((lane & k) == 0);
                bool  lower = ((lane & j) == 0);
                x = (up == lower) ? fminf(x, y) : fmaxf(x, y);
            }
        }
        s_wm[lane] = x;  // ascending
    }
    __syncthreads();

    // ---------------- Phase 1: fused NEG-fill + candidate collection ----------------
    const float4* rin4  = reinterpret_cast<const float4*>(rin);
    float4*       rout4 = reinterpret_cast<float4*>(rout);
    const int n4 = kVocab / 4;
    const float4 neg4 = make_float4(kNeg, kNeg, kNeg, kNeg);

    int rank = 7;  // 8th-largest warp max; expected exceedance ~1000
    if (tid == 0) { s_cnt = 0; s_T = s_wm[31 - rank]; }
    __syncthreads();
    float T = s_T;

#define PUSH_CAND(val, idx)                                                     \
    if ((val) > T) {                                                            \
        int p = atomicAdd(&s_cnt, 1);                                           \
        if (p < kCap)                                                           \
            s_cand[p] = ((unsigned long long)f2key(val) << 32) | (unsigned)(idx); \
    }

#pragma unroll 4
    for (int i = tid; i < n4; i += kThreads) {
        float4 x = rin4[i];
        rout4[i] = neg4;  // fill (overwritten later only for <=50 kept slots)
        PUSH_CAND(x.x, 4 * i);
        PUSH_CAND(x.y, 4 * i + 1);
        PUSH_CAND(x.z, 4 * i + 2);
        PUSH_CAND(x.w, 4 * i + 3);
    }
    __syncthreads();
    int cnt = s_cnt;

    // Retry ladder (essentially never taken for continuous data).
    for (int attempt = 0; attempt < 4 && (cnt < kTopK || cnt > kCap); ++attempt) {
        if (cnt < kTopK) rank = (rank < 31) ? (rank * 2 + 1) : 31;  // lower threshold
        else             rank = rank >> 1;                           // raise threshold
        __syncthreads();
        if (tid == 0) { s_cnt = 0; s_T = s_wm[31 - rank]; }
        __syncthreads();
        T = s_T;
        for (int i = tid; i < n4; i += kThreads) {
            float4 x = rin4[i];
            PUSH_CAND(x.x, 4 * i);
            PUSH_CAND(x.y, 4 * i + 1);
            PUSH_CAND(x.z, 4 * i + 2);
            PUSH_CAND(x.w, 4 * i + 3);
        }
        __syncthreads();
        cnt = s_cnt;
    }
#undef PUSH_CAND

    int n = cnt < kCap ? cnt : kCap;

    // ---------------- Phase 2: bitonic sort candidates (descending) ----------------
    int npad = 64;
    while (npad < n) npad <<= 1;
    for (int i = n + tid; i < npad; i += kThreads) s_cand[i] = 0ull;  // key 0 < any real key
    __syncthreads();

    for (int k = 2; k <= npad; k <<= 1) {
        for (int j = k >> 1; j > 0; j >>= 1) {
            for (int i = tid; i < npad; i += kThreads) {
                int p = i ^ j;
                if (p > i) {
                    unsigned long long a = s_cand[i];
                    unsigned long long b = s_cand[p];
                    bool desc = ((i & k) == 0);
                    if (desc ? (a < b) : (a > b)) { s_cand[i] = b; s_cand[p] = a; }
                }
            }
            __syncthreads();
        }
    }

    // ---------------- Phase 3: softmax cum-prob over top-50, find kept count ----------------
    if (tid == 0) {
        int lim = (n < kTopK) ? n : kTopK;
        int kk = 0;
        if (lim > 0) {
            float m = key2f((unsigned)(s_cand[0] >> 32));
            float Z = 0.f;
            for (int j = 0; j < lim; ++j) {
                float vj = key2f((unsigned)(s_cand[j] >> 32));
                float e  = expf(vj - m);
                s_ex[j]  = e;
                Z += e;
            }
            // keep token j iff j==0 or cum_{j-1} <= p  (cum = sum of probs, prefix order)
            float cum = 0.f;
            for (int j = 0; j < lim; ++j) {
                if (j > 0 && cum > kTopP) break;
                kk = j + 1;
                cum += s_ex[j] / Z;
            }
        }
        s_k = kk;
    }
    __syncthreads();

    // ---------------- Phase 4: scatter kept values over the NEG fill ----------------
    if (tid < s_k) {
        unsigned long long c = s_cand[tid];
        int idx = (int)(c & 0xFFFFFFFFu);
        rout[idx] = key2f((unsigned)(c >> 32));
    }
}

extern "C" void kernel_launch(void* const* d_in, const int* in_sizes, int n_in,
                              void* d_out, int out_size) {
    const float* in = (const float*)d_in[0];
    float* out = (float*)d_out;
    int rows = in_sizes[0] / kVocab;
    topk_topp_kernel<<<rows, kThreads>>>(in, out);
}

// round 2
// speedup vs baseline: 1.1129x; 1.1129x over previous
#include <cuda_runtime.h>
#include <cstdint>

static constexpr int   kVocab   = 128000;
static constexpr int   kTopK    = 50;
static constexpr float kTopP    = 0.9f;
static constexpr float kNeg     = -1000000000.0f;
static constexpr int   kThreads = 1024;
static constexpr int   kCap     = 4096;   // candidate buffer capacity (shared)

// Order-preserving float -> uint32 key (monotone increasing).
__device__ __forceinline__ unsigned f2key(float f) {
    unsigned b = __float_as_uint(f);
    return (b & 0x80000000u) ? ~b : (b | 0x80000000u);
}
__device__ __forceinline__ float key2f(unsigned k) {
    unsigned b = (k & 0x80000000u) ? (k & 0x7FFFFFFFu) : ~k;
    return __uint_as_float(b);
}

__global__ void __launch_bounds__(kThreads, 2)
topk_topp_kernel(const float* __restrict__ in, float* __restrict__ out) {
    __shared__ unsigned long long s_cand[kCap];
    __shared__ float s_wm[32];       // sorted (ascending) warp maxima of samples
    __shared__ float s_ex[kTopK];    // exp(v - max) for top tokens
    __shared__ int   s_cnt;
    __shared__ float s_T;
    __shared__ int   s_k;

    const int row  = blockIdx.x;
    const float* rin  = in  + (long long)row * kVocab;
    float*       rout = out + (long long)row * kVocab;
    const int tid  = threadIdx.x;
    const int lane = tid & 31;
    const int wid  = tid >> 5;

    // ---------------- Phase 0: sample-based threshold estimate ----------------
    // 1024 strided samples -> 32 warp maxima -> sort 32 values in warp 0.
    float sv = __ldcs(&rin[tid * (kVocab / kThreads)]);
#pragma unroll
    for (int o = 16; o > 0; o >>= 1)
        sv = fmaxf(sv, __shfl_xor_sync(0xffffffffu, sv, o));
    if (lane == 0) s_wm[wid] = sv;
    __syncthreads();
    if (wid == 0) {
        float x = s_wm[lane];
#pragma unroll
        for (int k = 2; k <= 32; k <<= 1) {
#pragma unroll
            for (int j = k >> 1; j > 0; j >>= 1) {
                float y     = __shfl_xor_sync(0xffffffffu, x, j);
                bool  up    = ((lane & k) == 0);
                bool  lower = ((lane & j) == 0);
                x = (up == lower) ? fminf(x, y) : fmaxf(x, y);
            }
        }
        s_wm[lane] = x;  // ascending
    }
    __syncthreads();

    // ---------------- Phase 1: fused NEG-fill + candidate collection ----------------
    const float4* rin4  = reinterpret_cast<const float4*>(rin);
    float4*       rout4 = reinterpret_cast<float4*>(rout);
    const int n4 = kVocab / 4;
    const float4 neg4 = make_float4(kNeg, kNeg, kNeg, kNeg);

    int rank = 7;  // 8th-largest warp max; expected exceedance ~1000-2000
    if (tid == 0) { s_cnt = 0; s_T = s_wm[31 - rank]; }
    __syncthreads();
    float T = s_T;

#define PUSH_CAND(val, idx)                                                     \
    if ((val) > T) {                                                            \
        int p = atomicAdd(&s_cnt, 1);                                           \
        if (p < kCap)                                                           \
            s_cand[p] = ((unsigned long long)f2key(val) << 32) | (unsigned)(idx); \
    }

#pragma unroll 2
    for (int i = tid; i < n4; i += kThreads) {
        float4 x = __ldcs(&rin4[i]);
        __stcs(&rout4[i], neg4);  // fill (overwritten later only for <=50 kept slots)
        PUSH_CAND(x.x, 4 * i);
        PUSH_CAND(x.y, 4 * i + 1);
        PUSH_CAND(x.z, 4 * i + 2);
        PUSH_CAND(x.w, 4 * i + 3);
    }
    __syncthreads();
    int cnt = s_cnt;

    // Retry ladder (essentially never taken for continuous data).
    for (int attempt = 0; attempt < 4 && (cnt < kTopK || cnt > kCap); ++attempt) {
        if (cnt < kTopK) rank = (rank < 31) ? (rank * 2 + 1) : 31;  // lower threshold
        else             rank = rank >> 1;                           // raise threshold
        __syncthreads();
        if (tid == 0) { s_cnt = 0; s_T = s_wm[31 - rank]; }
        __syncthreads();
        T = s_T;
        for (int i = tid; i < n4; i += kThreads) {
            float4 x = __ldcs(&rin4[i]);
            PUSH_CAND(x.x, 4 * i);
            PUSH_CAND(x.y, 4 * i + 1);
            PUSH_CAND(x.z, 4 * i + 2);
            PUSH_CAND(x.w, 4 * i + 3);
        }
        __syncthreads();
        cnt = s_cnt;
    }
#undef PUSH_CAND

    int n = cnt < kCap ? cnt : kCap;

    // ---------------- Phase 2: bitonic sort candidates (descending) ----------------
    int npad = 64;
    while (npad < n) npad <<= 1;
    for (int i = n + tid; i < npad; i += kThreads) s_cand[i] = 0ull;  // key 0 < any real key
    __syncthreads();

    for (int k = 2; k <= npad; k <<= 1) {
        for (int j = k >> 1; j > 0; j >>= 1) {
            for (int i = tid; i < npad; i += kThreads) {
                int p = i ^ j;
                if (p > i) {
                    unsigned long long a = s_cand[i];
                    unsigned long long b = s_cand[p];
                    bool desc = ((i & k) == 0);
                    if (desc ? (a < b) : (a > b)) { s_cand[i] = b; s_cand[p] = a; }
                }
            }
            __syncthreads();
        }
    }

    // ---------------- Phase 3: softmax cum-prob over top-50, find kept count ----------------
    if (tid == 0) {
        int lim = (n < kTopK) ? n : kTopK;
        int kk = 0;
        if (lim > 0) {
            float m = key2f((unsigned)(s_cand[0] >> 32));
            float Z = 0.f;
            for (int j = 0; j < lim; ++j) {
                float vj = key2f((unsigned)(s_cand[j] >> 32));
                float e  = expf(vj - m);
                s_ex[j]  = e;
                Z += e;
            }
            // keep token j iff j==0 or cum_{j-1} <= p  (cum = sum of probs, prefix order)
            float cum = 0.f;
            for (int j = 0; j < lim; ++j) {
                if (j > 0 && cum > kTopP) break;
                kk = j + 1;
                cum += s_ex[j] / Z;
            }
        }
        s_k = kk;
    }
    __syncthreads();

    // ---------------- Phase 4: scatter kept values over the NEG fill ----------------
    if (tid < s_k) {
        unsigned long long c = s_cand[tid];
        int idx = (int)(c & 0xFFFFFFFFu);
        rout[idx] = key2f((unsigned)(c >> 32));
    }
}

extern "C" void kernel_launch(void* const* d_in, const int* in_sizes, int n_in,
                              void* d_out, int out_size) {
    const float* in = (const float*)d_in[0];
    float* out = (float*)d_out;
    int rows = in_sizes[0] / kVocab;
    topk_topp_kernel<<<rows, kThreads>>>(in, out);
}